// round 11
// baseline (speedup 1.0000x reference)
#include <cuda_runtime.h>
#include <cuda_bf16.h>
#include <math.h>

// Problem constants: inputs [4096, 2048] fp32, targets [4096]
#define NN 4096
#define DD 2048                 // K = 2048 bf16 (hi-only; lo contributes < 2^-18)
#define BM 128
#define BN 128
#define BK 64
#define ROWB 144                // 128B data + 16B pad -> conflict-free ldsm phases
#define TILE_A_BYTES (BM * ROWB)            // 18432
#define TILE_B_BYTES (BN * ROWB)            // 18432
#define STAGE_BYTES (TILE_A_BYTES + TILE_B_BYTES)   // 36864
#define SMEM_DYN (2 * STAGE_BYTES)          // 73728 -> 3 CTAs/SM
#define NTILES 528              // lower triangle incl. diagonal of 32x32 tiles

// Scratch (no cudaMalloc allowed)
__device__ __nv_bfloat16 g_hi[(size_t)NN * DD];   // 16MB, row-major
__device__ float        g_sq[NN];
__device__ int          g_tgt[NN];
__device__ unsigned int g_ap[NN];
__device__ unsigned int g_an[NN];

// ---------------------------------------------------------------------------
__device__ __forceinline__ unsigned s2u(const void* p) {
    unsigned a;
    asm("{ .reg .u64 t; cvta.to.shared.u64 t, %1; cvt.u32.u64 %0, t; }" : "=r"(a) : "l"(p));
    return a;
}
__device__ __forceinline__ void cpa16(unsigned dst, const void* src) {
    unsigned long long g;
    asm("cvta.to.global.u64 %0, %1;" : "=l"(g) : "l"(src));
    asm volatile("cp.async.cg.shared.global [%0], [%1], 16;" :: "r"(dst), "l"(g));
}
__device__ __forceinline__ void ldsm4(unsigned* r, unsigned addr) {
    asm volatile("ldmatrix.sync.aligned.m8n8.x4.shared.b16 {%0,%1,%2,%3}, [%4];"
        : "=r"(r[0]), "=r"(r[1]), "=r"(r[2]), "=r"(r[3]) : "r"(addr));
}
__device__ __forceinline__ void mma16816(float* c, const unsigned* a, unsigned b0, unsigned b1) {
    asm volatile("mma.sync.aligned.m16n8k16.row.col.f32.bf16.bf16.f32 "
        "{%0,%1,%2,%3}, {%4,%5,%6,%7}, {%8,%9}, {%0,%1,%2,%3};"
        : "+f"(c[0]), "+f"(c[1]), "+f"(c[2]), "+f"(c[3])
        : "r"(a[0]), "r"(a[1]), "r"(a[2]), "r"(a[3]), "r"(b0), "r"(b1));
}

// ---------------------------------------------------------------------------
// Targets: int64 vs int32 detection (proven in passing baselines)
__global__ void tgt_kernel(const int* __restrict__ t) {
    __shared__ int is64;
    if (threadIdx.x == 0) is64 = 1;
    __syncthreads();
    for (int i = threadIdx.x; i < NN / 2; i += blockDim.x)
        if (t[2 * i + 1] != 0) is64 = 0;
    __syncthreads();
    const int e = is64;
    for (int i = threadIdx.x; i < NN; i += blockDim.x)
        g_tgt[i] = e ? t[2 * i] : t[i];
}

// fp32 -> bf16 hi, row-major; fused exact fp32 row norms + ap/an init.
__global__ void conv_kernel(const float* __restrict__ A) {
    const int i = blockIdx.x;
    const int t = threadIdx.x;  // 0..255, cols [8t, 8t+8)
    if (t == 0) { g_ap[i] = 0u; g_an[i] = 0x7f800000u; }
    const float4* ap = (const float4*)(A + (size_t)i * DD + t * 8);
    float4 v0 = ap[0], v1 = ap[1];
    float x[8] = {v0.x, v0.y, v0.z, v0.w, v1.x, v1.y, v1.z, v1.w};

    float s = 0.f;
    unsigned uh[4];
    #pragma unroll
    for (int q = 0; q < 4; q++) {
        float a0 = x[2*q], a1 = x[2*q+1];
        s += a0 * a0 + a1 * a1;
        __nv_bfloat16 h0 = __float2bfloat16_rn(a0);
        __nv_bfloat16 h1 = __float2bfloat16_rn(a1);
        uh[q] = (unsigned)__bfloat16_as_ushort(h0) | ((unsigned)__bfloat16_as_ushort(h1) << 16);
    }
    *(uint4*)(g_hi + (size_t)i * DD + t * 8) = make_uint4(uh[0], uh[1], uh[2], uh[3]);

    #pragma unroll
    for (int o = 16; o > 0; o >>= 1) s += __shfl_xor_sync(0xffffffffu, s, o);
    __shared__ float ws[8];
    const int lane = t & 31, w = t >> 5;
    if (lane == 0) ws[w] = s;
    __syncthreads();
    if (t == 0) {
        float tot = 0.f;
        #pragma unroll
        for (int k = 0; k < 8; k++) tot += ws[k];
        g_sq[i] = tot;
    }
}

// ---------------------------------------------------------------------------
// Fused Gram GEMM (mma.sync bf16, 128x128 block tile, K=2048) + hard mining.
// 128 threads = 4 warps in 2x2, warp tile 64x64 (32 HMMA : 8 LDSM per k16);
// 3 CTAs/SM. B-fragments double-buffered (2 live) to fit the 170-reg cap.
// ---------------------------------------------------------------------------
__global__ void __launch_bounds__(128, 3) gram_kernel() {
    extern __shared__ unsigned char smem_dyn[];
    __shared__ unsigned s_rap[BM], s_ran[BM], s_cap[BN], s_can[BN];

    const int tid = threadIdx.x, lane = tid & 31, wid = tid >> 5;
    const int wm = wid >> 1, wn = wid & 1;

    // lower-triangle tile decode: id = mt(mt+1)/2 + nt
    int mt = 0, rem = blockIdx.x;
    while (rem >= mt + 1) { rem -= mt + 1; mt++; }
    const int nt = rem;
    const int m0 = mt * BM, n0 = nt * BN;

    const unsigned sbase = s2u(smem_dyn);
    const __nv_bfloat16* hi = g_hi;

    s_rap[tid] = 0u; s_ran[tid] = 0x7f800000u;   // BM == 128 == blockDim
    s_cap[tid] = 0u; s_can[tid] = 0x7f800000u;

    float acc[4][8][4];
    #pragma unroll
    for (int a = 0; a < 4; a++)
        #pragma unroll
        for (int b = 0; b < 8; b++)
            #pragma unroll
            for (int c = 0; c < 4; c++) acc[a][b][c] = 0.f;

    // A: 128 rows x 8 quads = 1024 -> 8/thread; B likewise
    #define LOAD_STAGE(s, k0) do {                                              \
        const unsigned sA_ = sbase + (s) * STAGE_BYTES;                         \
        const unsigned sB_ = sA_ + TILE_A_BYTES;                                \
        _Pragma("unroll")                                                       \
        for (int s8 = 0; s8 < 8; s8++) {                                        \
            const int idx = tid + s8 * 128;                                     \
            const int r = idx >> 3, q = idx & 7;                                \
            cpa16(sA_ + r * ROWB + q * 16, hi + (size_t)(m0 + r) * DD + (k0) + q * 8); \
            cpa16(sB_ + r * ROWB + q * 16, hi + (size_t)(n0 + r) * DD + (k0) + q * 8); \
        }                                                                       \
    } while (0)

    LOAD_STAGE(0, 0);
    asm volatile("cp.async.commit_group;" ::: "memory");

    const int NK = DD / BK;  // 32
    const int rr = lane & 15;
    const unsigned coff = ((lane >> 4) << 4);      // +16B for hi half-warp

    int slot = 0;
    for (int ks = 0; ks < NK; ks++) {
        asm volatile("cp.async.wait_group 0;" ::: "memory");
        __syncthreads();
        if (ks + 1 < NK) LOAD_STAGE(slot ^ 1, (ks + 1) * BK);
        asm volatile("cp.async.commit_group;" ::: "memory");

        const unsigned stA = sbase + slot * STAGE_BYTES + (wm * 64 + rr) * ROWB;
        const unsigned stB = sbase + slot * STAGE_BYTES + TILE_A_BYTES + (wn * 64 + rr) * ROWB;
        #pragma unroll
        for (int h = 0; h < 4; h++) {
            const unsigned kb = h * 32 + coff;     // byte offset of k16 chunk
            unsigned a[4][4];
            #pragma unroll
            for (int mb = 0; mb < 4; mb++) ldsm4(a[mb], stA + mb * (16 * ROWB) + kb);
            unsigned b[2][4];
            ldsm4(b[0], stB + kb);
            #pragma unroll
            for (int g = 0; g < 4; g++) {
                if (g < 3) ldsm4(b[(g + 1) & 1], stB + (g + 1) * (16 * ROWB) + kb);
                const unsigned* bg = b[g & 1];
                #pragma unroll
                for (int mb = 0; mb < 4; mb++) {
                    mma16816(acc[mb][2*g],     a[mb], bg[0], bg[2]);
                    mma16816(acc[mb][2*g + 1], a[mb], bg[1], bg[3]);
                }
            }
        }
        slot ^= 1;
    }

    // ---- epilogue: distances + dual-direction mining ----
    const float FINF = __int_as_float(0x7f800000);
    float sqj[16]; int tj[16];
    #pragma unroll
    for (int nb = 0; nb < 8; nb++)
        #pragma unroll
        for (int e = 0; e < 2; e++) {
            const int j = n0 + wn * 64 + nb * 8 + (lane & 3) * 2 + e;
            sqj[nb*2+e] = g_sq[j];
            tj[nb*2+e]  = g_tgt[j];
        }
    float cap[16], can[16];
    #pragma unroll
    for (int k = 0; k < 16; k++) { cap[k] = 0.f; can[k] = FINF; }

    #pragma unroll
    for (int mb = 0; mb < 4; mb++) {
        const int i0 = m0 + wm * 64 + mb * 16 + (lane >> 2);
        const float sqi0 = g_sq[i0], sqi1 = g_sq[i0 + 8];
        const int   ti0  = g_tgt[i0], ti1 = g_tgt[i0 + 8];
        float rap0 = 0.f, ran0 = FINF, rap1 = 0.f, ran1 = FINF;
        #pragma unroll
        for (int nb = 0; nb < 8; nb++) {
            #pragma unroll
            for (int e = 0; e < 2; e++) {
                const int   k  = nb * 2 + e;
                const float da = sqrtf(fmaxf(sqi0 + sqj[k] - 2.f * acc[mb][nb][e],     1e-12f));
                const float db = sqrtf(fmaxf(sqi1 + sqj[k] - 2.f * acc[mb][nb][2 + e], 1e-12f));
                if (ti0 == tj[k]) { rap0 = fmaxf(rap0, da); cap[k] = fmaxf(cap[k], da); }
                else              { ran0 = fminf(ran0, da); can[k] = fminf(can[k], da); }
                if (ti1 == tj[k]) { rap1 = fmaxf(rap1, db); cap[k] = fmaxf(cap[k], db); }
                else              { ran1 = fminf(ran1, db); can[k] = fminf(can[k], db); }
            }
        }
        #pragma unroll
        for (int o = 1; o <= 2; o <<= 1) {
            rap0 = fmaxf(rap0, __shfl_xor_sync(0xffffffffu, rap0, o));
            ran0 = fminf(ran0, __shfl_xor_sync(0xffffffffu, ran0, o));
            rap1 = fmaxf(rap1, __shfl_xor_sync(0xffffffffu, rap1, o));
            ran1 = fminf(ran1, __shfl_xor_sync(0xffffffffu, ran1, o));
        }
        if ((lane & 3) == 0) {
            const int li = wm * 64 + mb * 16 + (lane >> 2);
            atomicMax(&s_rap[li],     __float_as_uint(rap0));
            atomicMin(&s_ran[li],     __float_as_uint(ran0));
            atomicMax(&s_rap[li + 8], __float_as_uint(rap1));
            atomicMin(&s_ran[li + 8], __float_as_uint(ran1));
        }
    }
    if (mt != nt) {   // column-direction mining (d symmetric); diagonal redundant
        #pragma unroll
        for (int k = 0; k < 16; k++) {
            #pragma unroll
            for (int o = 4; o <= 16; o <<= 1) {
                cap[k] = fmaxf(cap[k], __shfl_xor_sync(0xffffffffu, cap[k], o));
                can[k] = fminf(can[k], __shfl_xor_sync(0xffffffffu, can[k], o));
            }
        }
        if ((lane >> 2) == 0) {
            #pragma unroll
            for (int nb = 0; nb < 8; nb++)
                #pragma unroll
                for (int e = 0; e < 2; e++) {
                    const int lj = wn * 64 + nb * 8 + (lane & 3) * 2 + e;
                    atomicMax(&s_cap[lj], __float_as_uint(cap[nb*2+e]));
                    atomicMin(&s_can[lj], __float_as_uint(can[nb*2+e]));
                }
        }
    }
    __syncthreads();
    atomicMax(&g_ap[m0 + tid], s_rap[tid]);
    atomicMin(&g_an[m0 + tid], s_ran[tid]);
    if (mt != nt) {
        atomicMax(&g_ap[n0 + tid], s_cap[tid]);
        atomicMin(&g_an[n0 + tid], s_can[tid]);
    }
    #undef LOAD_STAGE
}

// ---------------------------------------------------------------------------
__global__ void finalize_kernel(float* __restrict__ out) {
    float l = 0.f, p = 0.f;
    for (int i = threadIdx.x; i < NN; i += blockDim.x) {
        const float a = __uint_as_float(g_ap[i]);
        const float n = __uint_as_float(g_an[i]);
        l += fmaxf(a - n + 0.3f, 0.f);
        p += (n > a) ? 1.f : 0.f;
    }
    #pragma unroll
    for (int o = 16; o > 0; o >>= 1) {
        l += __shfl_xor_sync(0xffffffffu, l, o);
        p += __shfl_xor_sync(0xffffffffu, p, o);
    }
    __shared__ float wl[32], wp[32];
    const int lane = threadIdx.x & 31, w = threadIdx.x >> 5;
    if (lane == 0) { wl[w] = l; wp[w] = p; }
    __syncthreads();
    if (w == 0) {
        const int nw = blockDim.x >> 5;
        float L = (lane < nw) ? wl[lane] : 0.f;
        float P = (lane < nw) ? wp[lane] : 0.f;
        #pragma unroll
        for (int o = 16; o > 0; o >>= 1) {
            L += __shfl_xor_sync(0xffffffffu, L, o);
            P += __shfl_xor_sync(0xffffffffu, P, o);
        }
        if (lane == 0) { out[0] = L / (float)NN; out[1] = P / (float)NN; }
    }
}

// ---------------------------------------------------------------------------
extern "C" void kernel_launch(void* const* d_in, const int* in_sizes, int n_in,
                              void* d_out, int out_size) {
    const float* A = (const float*)d_in[0];
    const int*   t = (const int*)d_in[1];
    float*     out = (float*)d_out;

    cudaFuncSetAttribute(gram_kernel, cudaFuncAttributeMaxDynamicSharedMemorySize, SMEM_DYN);

    tgt_kernel<<<1, 1024>>>(t);
    conv_kernel<<<NN, 256>>>(A);
    gram_kernel<<<NTILES, 128, SMEM_DYN>>>();
    finalize_kernel<<<1, 1024>>>(out);
}

// round 12
// speedup vs baseline: 1.0667x; 1.0667x over previous
#include <cuda_runtime.h>
#include <cuda_bf16.h>
#include <math.h>

// Problem constants: inputs [4096, 2048] fp32, targets [4096]
#define NN 4096
#define DD 2048                 // K = 2048 bf16 (hi-only; lo contributes < 2^-18)
#define BM 64
#define BN 128
#define BK 32
#define STAGES 3
#define ROWB 80                 // 64B data + 16B pad: r*5 mod 8 permutation -> conflict-free
#define TILE_A_BYTES (BM * ROWB)            // 5120
#define TILE_B_BYTES (BN * ROWB)            // 10240
#define STAGE_BYTES (TILE_A_BYTES + TILE_B_BYTES)   // 15360
#define SMEM_DYN (STAGES * STAGE_BYTES)     // 46080 -> 4 CTAs/SM
#define NTILES 1056             // tiles (mt,nt2), 64-row x 128-col, mt >= 2*nt2

// Scratch (no cudaMalloc allowed)
__device__ __nv_bfloat16 g_hi[(size_t)NN * DD];   // 16MB, row-major
__device__ float        g_sq[NN];
__device__ int          g_tgt[NN];
__device__ unsigned int g_ap[NN];
__device__ unsigned int g_an[NN];

// ---------------------------------------------------------------------------
__device__ __forceinline__ unsigned s2u(const void* p) {
    unsigned a;
    asm("{ .reg .u64 t; cvta.to.shared.u64 t, %1; cvt.u32.u64 %0, t; }" : "=r"(a) : "l"(p));
    return a;
}
__device__ __forceinline__ void cpa16(unsigned dst, const void* src) {
    unsigned long long g;
    asm("cvta.to.global.u64 %0, %1;" : "=l"(g) : "l"(src));
    asm volatile("cp.async.cg.shared.global [%0], [%1], 16;" :: "r"(dst), "l"(g));
}
__device__ __forceinline__ void ldsm4(unsigned* r, unsigned addr) {
    asm volatile("ldmatrix.sync.aligned.m8n8.x4.shared.b16 {%0,%1,%2,%3}, [%4];"
        : "=r"(r[0]), "=r"(r[1]), "=r"(r[2]), "=r"(r[3]) : "r"(addr));
}
__device__ __forceinline__ void mma16816(float* c, const unsigned* a, unsigned b0, unsigned b1) {
    asm volatile("mma.sync.aligned.m16n8k16.row.col.f32.bf16.bf16.f32 "
        "{%0,%1,%2,%3}, {%4,%5,%6,%7}, {%8,%9}, {%0,%1,%2,%3};"
        : "+f"(c[0]), "+f"(c[1]), "+f"(c[2]), "+f"(c[3])
        : "r"(a[0]), "r"(a[1]), "r"(a[2]), "r"(a[3]), "r"(b0), "r"(b1));
}

// ---------------------------------------------------------------------------
// Targets: int64 vs int32 detection (proven in passing baselines)
__global__ void tgt_kernel(const int* __restrict__ t) {
    __shared__ int is64;
    if (threadIdx.x == 0) is64 = 1;
    __syncthreads();
    for (int i = threadIdx.x; i < NN / 2; i += blockDim.x)
        if (t[2 * i + 1] != 0) is64 = 0;
    __syncthreads();
    const int e = is64;
    for (int i = threadIdx.x; i < NN; i += blockDim.x)
        g_tgt[i] = e ? t[2 * i] : t[i];
}

// fp32 -> bf16 hi, row-major; fused exact fp32 row norms + ap/an init.
__global__ void conv_kernel(const float* __restrict__ A) {
    const int i = blockIdx.x;
    const int t = threadIdx.x;  // 0..255, cols [8t, 8t+8)
    if (t == 0) { g_ap[i] = 0u; g_an[i] = 0x7f800000u; }
    const float4* ap = (const float4*)(A + (size_t)i * DD + t * 8);
    float4 v0 = ap[0], v1 = ap[1];
    float x[8] = {v0.x, v0.y, v0.z, v0.w, v1.x, v1.y, v1.z, v1.w};

    float s = 0.f;
    unsigned uh[4];
    #pragma unroll
    for (int q = 0; q < 4; q++) {
        float a0 = x[2*q], a1 = x[2*q+1];
        s += a0 * a0 + a1 * a1;
        __nv_bfloat16 h0 = __float2bfloat16_rn(a0);
        __nv_bfloat16 h1 = __float2bfloat16_rn(a1);
        uh[q] = (unsigned)__bfloat16_as_ushort(h0) | ((unsigned)__bfloat16_as_ushort(h1) << 16);
    }
    *(uint4*)(g_hi + (size_t)i * DD + t * 8) = make_uint4(uh[0], uh[1], uh[2], uh[3]);

    #pragma unroll
    for (int o = 16; o > 0; o >>= 1) s += __shfl_xor_sync(0xffffffffu, s, o);
    __shared__ float ws[8];
    const int lane = t & 31, w = t >> 5;
    if (lane == 0) ws[w] = s;
    __syncthreads();
    if (t == 0) {
        float tot = 0.f;
        #pragma unroll
        for (int k = 0; k < 8; k++) tot += ws[k];
        g_sq[i] = tot;
    }
}

// ---------------------------------------------------------------------------
// Fused Gram GEMM (mma.sync bf16, 64x128 block tile, K=2048) + hard mining.
// 128 threads = 4 warps (1x4), warp tile 64x32; 4 CTAs/SM; 3-stage cp.async
// pipeline with wait_group 1 (each stage has ~2 compute iterations of cover).
// ---------------------------------------------------------------------------
__global__ void __launch_bounds__(128, 4) gram_kernel() {
    extern __shared__ unsigned char smem_dyn[];
    __shared__ unsigned s_rap[BM], s_ran[BM], s_cap[BN], s_can[BN];

    const int tid = threadIdx.x, lane = tid & 31, wn = tid >> 5;

    // tile decode: (mt, nt2) with mt >= 2*nt2; 64-row tiles, 128-col tiles
    int nt2 = 0, rem = blockIdx.x;
    while (rem >= 64 - 2 * nt2) { rem -= 64 - 2 * nt2; nt2++; }
    const int mt = 2 * nt2 + rem;
    const int m0 = mt * BM, n0 = nt2 * BN;

    const unsigned sbase = s2u(smem_dyn);
    const __nv_bfloat16* hi = g_hi;

    if (tid < BM) { s_rap[tid] = 0u; s_ran[tid] = 0x7f800000u; }
    s_cap[tid] = 0u; s_can[tid] = 0x7f800000u;   // BN == 128 == blockDim

    float acc[4][4][4];
    #pragma unroll
    for (int a = 0; a < 4; a++)
        #pragma unroll
        for (int b = 0; b < 4; b++)
            #pragma unroll
            for (int c = 0; c < 4; c++) acc[a][b][c] = 0.f;

    // A: 64 rows x 4 quads = 256 -> 2/thread; B: 128 rows x 4 quads = 512 -> 4/thread
    #define LOAD_STAGE(s, k0) do {                                              \
        const unsigned sA_ = sbase + (s) * STAGE_BYTES;                         \
        const unsigned sB_ = sA_ + TILE_A_BYTES;                                \
        _Pragma("unroll")                                                       \
        for (int s2 = 0; s2 < 2; s2++) {                                        \
            const int idx = tid + s2 * 128;                                     \
            const int r = idx >> 2, q = idx & 3;                                \
            cpa16(sA_ + r * ROWB + q * 16, hi + (size_t)(m0 + r) * DD + (k0) + q * 8); \
        }                                                                       \
        _Pragma("unroll")                                                       \
        for (int s4 = 0; s4 < 4; s4++) {                                        \
            const int idx = tid + s4 * 128;                                     \
            const int r = idx >> 2, q = idx & 3;                                \
            cpa16(sB_ + r * ROWB + q * 16, hi + (size_t)(n0 + r) * DD + (k0) + q * 8); \
        }                                                                       \
    } while (0)

    LOAD_STAGE(0, 0);
    asm volatile("cp.async.commit_group;" ::: "memory");
    LOAD_STAGE(1, BK);
    asm volatile("cp.async.commit_group;" ::: "memory");

    const int NK = DD / BK;  // 64
    const int rr = lane & 15;
    const unsigned coff = ((lane >> 4) << 4);      // +16B for hi half-warp

    int slot = 0, nslot = 2;
    for (int ks = 0; ks < NK; ks++) {
        asm volatile("cp.async.wait_group 1;" ::: "memory");
        __syncthreads();
        // slot for ks+2 was freed: its data was consumed at ks-1, barrier above
        if (ks + 2 < NK) LOAD_STAGE(nslot, (ks + 2) * BK);
        asm volatile("cp.async.commit_group;" ::: "memory");

        const unsigned stA = sbase + slot * STAGE_BYTES + rr * ROWB;
        const unsigned stB = sbase + slot * STAGE_BYTES + TILE_A_BYTES + (wn * 32 + rr) * ROWB;
        #pragma unroll
        for (int h = 0; h < 2; h++) {
            const unsigned kb = h * 32 + coff;     // byte offset of k16 chunk
            unsigned a[4][4], bq[2][4];
            #pragma unroll
            for (int mb = 0; mb < 4; mb++) ldsm4(a[mb], stA + mb * (16 * ROWB) + kb);
            #pragma unroll
            for (int g = 0; g < 2; g++)    ldsm4(bq[g], stB + g * (16 * ROWB) + kb);
            #pragma unroll
            for (int mb = 0; mb < 4; mb++) {
                #pragma unroll
                for (int g = 0; g < 2; g++) {
                    mma16816(acc[mb][2*g],     a[mb], bq[g][0], bq[g][2]);
                    mma16816(acc[mb][2*g + 1], a[mb], bq[g][1], bq[g][3]);
                }
            }
        }
        slot = (slot + 1 == STAGES) ? 0 : slot + 1;
        nslot = (nslot + 1 == STAGES) ? 0 : nslot + 1;
    }

    // ---- epilogue: distances + dual-direction mining ----
    const float FINF = __int_as_float(0x7f800000);
    float sqj[8]; int tj[8];
    #pragma unroll
    for (int nb = 0; nb < 4; nb++)
        #pragma unroll
        for (int e = 0; e < 2; e++) {
            const int j = n0 + wn * 32 + nb * 8 + (lane & 3) * 2 + e;
            sqj[nb*2+e] = g_sq[j];
            tj[nb*2+e]  = g_tgt[j];
        }
    float cap[8], can[8];
    #pragma unroll
    for (int k = 0; k < 8; k++) { cap[k] = 0.f; can[k] = FINF; }

    #pragma unroll
    for (int mb = 0; mb < 4; mb++) {
        const int i0 = m0 + mb * 16 + (lane >> 2);
        const float sqi0 = g_sq[i0], sqi1 = g_sq[i0 + 8];
        const int   ti0  = g_tgt[i0], ti1 = g_tgt[i0 + 8];
        float rap0 = 0.f, ran0 = FINF, rap1 = 0.f, ran1 = FINF;
        #pragma unroll
        for (int nb = 0; nb < 4; nb++) {
            #pragma unroll
            for (int e = 0; e < 2; e++) {
                const int   k  = nb * 2 + e;
                const float da = sqrtf(fmaxf(sqi0 + sqj[k] - 2.f * acc[mb][nb][e],     1e-12f));
                const float db = sqrtf(fmaxf(sqi1 + sqj[k] - 2.f * acc[mb][nb][2 + e], 1e-12f));
                if (ti0 == tj[k]) { rap0 = fmaxf(rap0, da); cap[k] = fmaxf(cap[k], da); }
                else              { ran0 = fminf(ran0, da); can[k] = fminf(can[k], da); }
                if (ti1 == tj[k]) { rap1 = fmaxf(rap1, db); cap[k] = fmaxf(cap[k], db); }
                else              { ran1 = fminf(ran1, db); can[k] = fminf(can[k], db); }
            }
        }
        #pragma unroll
        for (int o = 1; o <= 2; o <<= 1) {
            rap0 = fmaxf(rap0, __shfl_xor_sync(0xffffffffu, rap0, o));
            ran0 = fminf(ran0, __shfl_xor_sync(0xffffffffu, ran0, o));
            rap1 = fmaxf(rap1, __shfl_xor_sync(0xffffffffu, rap1, o));
            ran1 = fminf(ran1, __shfl_xor_sync(0xffffffffu, ran1, o));
        }
        if ((lane & 3) == 0) {
            const int li = mb * 16 + (lane >> 2);
            atomicMax(&s_rap[li],     __float_as_uint(rap0));
            atomicMin(&s_ran[li],     __float_as_uint(ran0));
            atomicMax(&s_rap[li + 8], __float_as_uint(rap1));
            atomicMin(&s_ran[li + 8], __float_as_uint(ran1));
        }
    }
    // column-direction mining (d symmetric); idempotent with row direction
    #pragma unroll
    for (int k = 0; k < 8; k++) {
        #pragma unroll
        for (int o = 4; o <= 16; o <<= 1) {
            cap[k] = fmaxf(cap[k], __shfl_xor_sync(0xffffffffu, cap[k], o));
            can[k] = fminf(can[k], __shfl_xor_sync(0xffffffffu, can[k], o));
        }
    }
    if ((lane >> 2) == 0) {
        #pragma unroll
        for (int nb = 0; nb < 4; nb++)
            #pragma unroll
            for (int e = 0; e < 2; e++) {
                const int lj = wn * 32 + nb * 8 + (lane & 3) * 2 + e;
                atomicMax(&s_cap[lj], __float_as_uint(cap[nb*2+e]));
                atomicMin(&s_can[lj], __float_as_uint(can[nb*2+e]));
            }
    }
    __syncthreads();
    if (tid < BM) {
        atomicMax(&g_ap[m0 + tid], s_rap[tid]);
        atomicMin(&g_an[m0 + tid], s_ran[tid]);
    }
    atomicMax(&g_ap[n0 + tid], s_cap[tid]);
    atomicMin(&g_an[n0 + tid], s_can[tid]);
    #undef LOAD_STAGE
}

// ---------------------------------------------------------------------------
__global__ void finalize_kernel(float* __restrict__ out) {
    float l = 0.f, p = 0.f;
    for (int i = threadIdx.x; i < NN; i += blockDim.x) {
        const float a = __uint_as_float(g_ap[i]);
        const float n = __uint_as_float(g_an[i]);
        l += fmaxf(a - n + 0.3f, 0.f);
        p += (n > a) ? 1.f : 0.f;
    }
    #pragma unroll
    for (int o = 16; o > 0; o >>= 1) {
        l += __shfl_xor_sync(0xffffffffu, l, o);
        p += __shfl_xor_sync(0xffffffffu, p, o);
    }
    __shared__ float wl[32], wp[32];
    const int lane = threadIdx.x & 31, w = threadIdx.x >> 5;
    if (lane == 0) { wl[w] = l; wp[w] = p; }
    __syncthreads();
    if (w == 0) {
        const int nw = blockDim.x >> 5;
        float L = (lane < nw) ? wl[lane] : 0.f;
        float P = (lane < nw) ? wp[lane] : 0.f;
        #pragma unroll
        for (int o = 16; o > 0; o >>= 1) {
            L += __shfl_xor_sync(0xffffffffu, L, o);
            P += __shfl_xor_sync(0xffffffffu, P, o);
        }
        if (lane == 0) { out[0] = L / (float)NN; out[1] = P / (float)NN; }
    }
}

// ---------------------------------------------------------------------------
extern "C" void kernel_launch(void* const* d_in, const int* in_sizes, int n_in,
                              void* d_out, int out_size) {
    const float* A = (const float*)d_in[0];
    const int*   t = (const int*)d_in[1];
    float*     out = (float*)d_out;

    cudaFuncSetAttribute(gram_kernel, cudaFuncAttributeMaxDynamicSharedMemorySize, SMEM_DYN);

    tgt_kernel<<<1, 1024>>>(t);
    conv_kernel<<<NN, 256>>>(A);
    gram_kernel<<<NTILES, 128, SMEM_DYN>>>();
    finalize_kernel<<<1, 1024>>>(out);
}

// round 13
// speedup vs baseline: 1.1958x; 1.1210x over previous
#include <cuda_runtime.h>
#include <cuda_bf16.h>
#include <math.h>

// Problem constants: inputs [4096, 2048] fp32, targets [4096]
#define NN 4096
#define DD 2048                 // K = 2048 bf16 (hi-only; lo contributes < 2^-18)
#define BM 64
#define BN 128
#define BK 64
#define STAGES 2
#define ROWB 144                // 128B data + 16B pad -> conflict-free ldsm phases
#define TILE_A_BYTES (BM * ROWB)            // 9216
#define TILE_B_BYTES (BN * ROWB)            // 18432
#define STAGE_BYTES (TILE_A_BYTES + TILE_B_BYTES)   // 27648
#define SMEM_DYN (STAGES * STAGE_BYTES)     // 55296 -> 4 CTAs/SM
#define NTILES 1056             // tiles (mt,nt2), 64-row x 128-col, mt >= 2*nt2

// Scratch (no cudaMalloc allowed)
__device__ __nv_bfloat16 g_hi[(size_t)NN * DD];   // 16MB, row-major
__device__ float        g_sq[NN];
__device__ int          g_tgt[NN];
__device__ unsigned int g_ap[NN];   // hardest-positive d^2 (max), clamped positive
__device__ unsigned int g_an[NN];   // hardest-negative d^2 (min)

// ---------------------------------------------------------------------------
__device__ __forceinline__ unsigned s2u(const void* p) {
    unsigned a;
    asm("{ .reg .u64 t; cvta.to.shared.u64 t, %1; cvt.u32.u64 %0, t; }" : "=r"(a) : "l"(p));
    return a;
}
__device__ __forceinline__ void cpa16(unsigned dst, const void* src) {
    unsigned long long g;
    asm("cvta.to.global.u64 %0, %1;" : "=l"(g) : "l"(src));
    asm volatile("cp.async.cg.shared.global [%0], [%1], 16;" :: "r"(dst), "l"(g));
}
__device__ __forceinline__ void ldsm4(unsigned* r, unsigned addr) {
    asm volatile("ldmatrix.sync.aligned.m8n8.x4.shared.b16 {%0,%1,%2,%3}, [%4];"
        : "=r"(r[0]), "=r"(r[1]), "=r"(r[2]), "=r"(r[3]) : "r"(addr));
}
__device__ __forceinline__ void mma16816(float* c, const unsigned* a, unsigned b0, unsigned b1) {
    asm volatile("mma.sync.aligned.m16n8k16.row.col.f32.bf16.bf16.f32 "
        "{%0,%1,%2,%3}, {%4,%5,%6,%7}, {%8,%9}, {%0,%1,%2,%3};"
        : "+f"(c[0]), "+f"(c[1]), "+f"(c[2]), "+f"(c[3])
        : "r"(a[0]), "r"(a[1]), "r"(a[2]), "r"(a[3]), "r"(b0), "r"(b1));
}

// ---------------------------------------------------------------------------
// fp32 -> bf16 hi, row-major; fused exact fp32 row norms + ap/an init.
// Block 0 additionally normalizes targets (int64 vs int32 autodetect).
__global__ void conv_kernel(const float* __restrict__ A, const int* __restrict__ tgt) {
    const int i = blockIdx.x;
    const int t = threadIdx.x;  // 0..255, cols [8t, 8t+8)
    if (t == 0) { g_ap[i] = 0u; g_an[i] = 0x7f800000u; }

    const float4* ap = (const float4*)(A + (size_t)i * DD + t * 8);
    float4 v0 = ap[0], v1 = ap[1];
    float x[8] = {v0.x, v0.y, v0.z, v0.w, v1.x, v1.y, v1.z, v1.w};

    float s = 0.f;
    unsigned uh[4];
    #pragma unroll
    for (int q = 0; q < 4; q++) {
        float a0 = x[2*q], a1 = x[2*q+1];
        s += a0 * a0 + a1 * a1;
        __nv_bfloat16 h0 = __float2bfloat16_rn(a0);
        __nv_bfloat16 h1 = __float2bfloat16_rn(a1);
        uh[q] = (unsigned)__bfloat16_as_ushort(h0) | ((unsigned)__bfloat16_as_ushort(h1) << 16);
    }
    *(uint4*)(g_hi + (size_t)i * DD + t * 8) = make_uint4(uh[0], uh[1], uh[2], uh[3]);

    #pragma unroll
    for (int o = 16; o > 0; o >>= 1) s += __shfl_xor_sync(0xffffffffu, s, o);
    __shared__ float ws[8];
    __shared__ int is64;
    const int lane = t & 31, w = t >> 5;
    if (lane == 0) ws[w] = s;
    if (t == 0) is64 = 1;
    __syncthreads();
    if (t == 0) {
        float tot = 0.f;
        #pragma unroll
        for (int k = 0; k < 8; k++) tot += ws[k];
        g_sq[i] = tot;
    }
    if (i == 0) {   // block 0: target normalization
        for (int j = t; j < NN / 2; j += 256)
            if (tgt[2 * j + 1] != 0) is64 = 0;
        __syncthreads();
        const int e = is64;
        for (int j = t; j < NN; j += 256)
            g_tgt[j] = e ? tgt[2 * j] : tgt[j];
    }
}

// ---------------------------------------------------------------------------
// Fused Gram GEMM (mma.sync bf16, 64x128 block tile, K=2048) + hard mining
// on clamped squared distances (sqrt deferred to finalize; monotone-safe).
// 128 threads = 4 warps (1x4), warp tile 64x32; 4 CTAs/SM; 2-stage cp.async.
// ---------------------------------------------------------------------------
__global__ void __launch_bounds__(128, 4) gram_kernel() {
    extern __shared__ unsigned char smem_dyn[];
    __shared__ unsigned s_rap[BM], s_ran[BM], s_cap[BN], s_can[BN];

    const int tid = threadIdx.x, lane = tid & 31, wn = tid >> 5;

    // tile decode: (mt, nt2) with mt >= 2*nt2; 64-row tiles, 128-col tiles
    int nt2 = 0, rem = blockIdx.x;
    while (rem >= 64 - 2 * nt2) { rem -= 64 - 2 * nt2; nt2++; }
    const int mt = 2 * nt2 + rem;
    const int m0 = mt * BM, n0 = nt2 * BN;

    const unsigned sbase = s2u(smem_dyn);
    const __nv_bfloat16* hi = g_hi;

    if (tid < BM) { s_rap[tid] = 0u; s_ran[tid] = 0x7f800000u; }
    s_cap[tid] = 0u; s_can[tid] = 0x7f800000u;   // BN == 128 == blockDim

    float acc[4][4][4];
    #pragma unroll
    for (int a = 0; a < 4; a++)
        #pragma unroll
        for (int b = 0; b < 4; b++)
            #pragma unroll
            for (int c = 0; c < 4; c++) acc[a][b][c] = 0.f;

    // A: 64 rows x 8 quads = 512 -> 4/thread; B: 128 rows x 8 quads = 1024 -> 8/thread
    #define LOAD_STAGE(s, k0) do {                                              \
        const unsigned sA_ = sbase + (s) * STAGE_BYTES;                         \
        const unsigned sB_ = sA_ + TILE_A_BYTES;                                \
        _Pragma("unroll")                                                       \
        for (int s4 = 0; s4 < 4; s4++) {                                        \
            const int idx = tid + s4 * 128;                                     \
            const int r = idx >> 3, q = idx & 7;                                \
            cpa16(sA_ + r * ROWB + q * 16, hi + (size_t)(m0 + r) * DD + (k0) + q * 8); \
        }                                                                       \
        _Pragma("unroll")                                                       \
        for (int s8 = 0; s8 < 8; s8++) {                                        \
            const int idx = tid + s8 * 128;                                     \
            const int r = idx >> 3, q = idx & 7;                                \
            cpa16(sB_ + r * ROWB + q * 16, hi + (size_t)(n0 + r) * DD + (k0) + q * 8); \
        }                                                                       \
    } while (0)

    LOAD_STAGE(0, 0);
    asm volatile("cp.async.commit_group;" ::: "memory");

    const int NK = DD / BK;  // 32
    const int rr = lane & 15;
    const unsigned coff = ((lane >> 4) << 4);      // +16B for hi half-warp
    const int hrot = (wn & 1) << 1;                // per-warp h-phase rotation

    int slot = 0;
    for (int ks = 0; ks < NK; ks++) {
        asm volatile("cp.async.wait_group 0;" ::: "memory");
        __syncthreads();
        // issue next stage immediately (slot^1 freed by the barrier above)
        if (ks + 1 < NK) LOAD_STAGE(slot ^ 1, (ks + 1) * BK);
        asm volatile("cp.async.commit_group;" ::: "memory");

        const unsigned stA = sbase + slot * STAGE_BYTES + rr * ROWB;
        const unsigned stB = sbase + slot * STAGE_BYTES + TILE_A_BYTES + (wn * 32 + rr) * ROWB;
        #pragma unroll
        for (int hh = 0; hh < 4; hh++) {
            const int h = (hh + hrot) & 3;
            const unsigned kb = h * 32 + coff;     // byte offset of k16 chunk
            unsigned a[4][4], bq[2][4];
            #pragma unroll
            for (int mb = 0; mb < 4; mb++) ldsm4(a[mb], stA + mb * (16 * ROWB) + kb);
            #pragma unroll
            for (int g = 0; g < 2; g++)    ldsm4(bq[g], stB + g * (16 * ROWB) + kb);
            #pragma unroll
            for (int mb = 0; mb < 4; mb++) {
                #pragma unroll
                for (int g = 0; g < 2; g++) {
                    mma16816(acc[mb][2*g],     a[mb], bq[g][0], bq[g][2]);
                    mma16816(acc[mb][2*g + 1], a[mb], bq[g][1], bq[g][3]);
                }
            }
        }
        slot ^= 1;
    }

    // ---- epilogue: clamped d^2 + dual-direction mining (sqrt deferred) ----
    const float FINF = __int_as_float(0x7f800000);
    float sqj[8]; int tj[8];
    #pragma unroll
    for (int nb = 0; nb < 4; nb++)
        #pragma unroll
        for (int e = 0; e < 2; e++) {
            const int j = n0 + wn * 32 + nb * 8 + (lane & 3) * 2 + e;
            sqj[nb*2+e] = g_sq[j];
            tj[nb*2+e]  = g_tgt[j];
        }
    float cap[8], can[8];
    #pragma unroll
    for (int k = 0; k < 8; k++) { cap[k] = 0.f; can[k] = FINF; }

    #pragma unroll
    for (int mb = 0; mb < 4; mb++) {
        const int i0 = m0 + mb * 16 + (lane >> 2);
        const float sqi0 = g_sq[i0], sqi1 = g_sq[i0 + 8];
        const int   ti0  = g_tgt[i0], ti1 = g_tgt[i0 + 8];
        float rap0 = 0.f, ran0 = FINF, rap1 = 0.f, ran1 = FINF;
        #pragma unroll
        for (int nb = 0; nb < 4; nb++) {
            #pragma unroll
            for (int e = 0; e < 2; e++) {
                const int   k  = nb * 2 + e;
                const float da = fmaxf(sqi0 + sqj[k] - 2.f * acc[mb][nb][e],     1e-12f);
                const float db = fmaxf(sqi1 + sqj[k] - 2.f * acc[mb][nb][2 + e], 1e-12f);
                if (ti0 == tj[k]) { rap0 = fmaxf(rap0, da); cap[k] = fmaxf(cap[k], da); }
                else              { ran0 = fminf(ran0, da); can[k] = fminf(can[k], da); }
                if (ti1 == tj[k]) { rap1 = fmaxf(rap1, db); cap[k] = fmaxf(cap[k], db); }
                else              { ran1 = fminf(ran1, db); can[k] = fminf(can[k], db); }
            }
        }
        #pragma unroll
        for (int o = 1; o <= 2; o <<= 1) {
            rap0 = fmaxf(rap0, __shfl_xor_sync(0xffffffffu, rap0, o));
            ran0 = fminf(ran0, __shfl_xor_sync(0xffffffffu, ran0, o));
            rap1 = fmaxf(rap1, __shfl_xor_sync(0xffffffffu, rap1, o));
            ran1 = fminf(ran1, __shfl_xor_sync(0xffffffffu, ran1, o));
        }
        if ((lane & 3) == 0) {
            const int li = mb * 16 + (lane >> 2);
            atomicMax(&s_rap[li],     __float_as_uint(rap0));
            atomicMin(&s_ran[li],     __float_as_uint(ran0));
            atomicMax(&s_rap[li + 8], __float_as_uint(rap1));
            atomicMin(&s_ran[li + 8], __float_as_uint(ran1));
        }
    }
    // column-direction mining (d^2 symmetric); idempotent with row direction
    #pragma unroll
    for (int k = 0; k < 8; k++) {
        #pragma unroll
        for (int o = 4; o <= 16; o <<= 1) {
            cap[k] = fmaxf(cap[k], __shfl_xor_sync(0xffffffffu, cap[k], o));
            can[k] = fminf(can[k], __shfl_xor_sync(0xffffffffu, can[k], o));
        }
    }
    if ((lane >> 2) == 0) {
        #pragma unroll
        for (int nb = 0; nb < 4; nb++)
            #pragma unroll
            for (int e = 0; e < 2; e++) {
                const int lj = wn * 32 + nb * 8 + (lane & 3) * 2 + e;
                atomicMax(&s_cap[lj], __float_as_uint(cap[nb*2+e]));
                atomicMin(&s_can[lj], __float_as_uint(can[nb*2+e]));
            }
    }
    __syncthreads();
    if (tid < BM) {
        atomicMax(&g_ap[m0 + tid], s_rap[tid]);
        atomicMin(&g_an[m0 + tid], s_ran[tid]);
    }
    atomicMax(&g_ap[n0 + tid], s_cap[tid]);
    atomicMin(&g_an[n0 + tid], s_can[tid]);
    #undef LOAD_STAGE
}

// ---------------------------------------------------------------------------
__global__ void finalize_kernel(float* __restrict__ out) {
    float l = 0.f, p = 0.f;
    for (int i = threadIdx.x; i < NN; i += blockDim.x) {
        const float a = sqrtf(__uint_as_float(g_ap[i]));
        const float n = sqrtf(__uint_as_float(g_an[i]));
        l += fmaxf(a - n + 0.3f, 0.f);
        p += (n > a) ? 1.f : 0.f;
    }
    #pragma unroll
    for (int o = 16; o > 0; o >>= 1) {
        l += __shfl_xor_sync(0xffffffffu, l, o);
        p += __shfl_xor_sync(0xffffffffu, p, o);
    }
    __shared__ float wl[32], wp[32];
    const int lane = threadIdx.x & 31, w = threadIdx.x >> 5;
    if (lane == 0) { wl[w] = l; wp[w] = p; }
    __syncthreads();
    if (w == 0) {
        const int nw = blockDim.x >> 5;
        float L = (lane < nw) ? wl[lane] : 0.f;
        float P = (lane < nw) ? wp[lane] : 0.f;
        #pragma unroll
        for (int o = 16; o > 0; o >>= 1) {
            L += __shfl_xor_sync(0xffffffffu, L, o);
            P += __shfl_xor_sync(0xffffffffu, P, o);
        }
        if (lane == 0) { out[0] = L / (float)NN; out[1] = P / (float)NN; }
    }
}

// ---------------------------------------------------------------------------
extern "C" void kernel_launch(void* const* d_in, const int* in_sizes, int n_in,
                              void* d_out, int out_size) {
    const float* A = (const float*)d_in[0];
    const int*   t = (const int*)d_in[1];
    float*     out = (float*)d_out;

    cudaFuncSetAttribute(gram_kernel, cudaFuncAttributeMaxDynamicSharedMemorySize, SMEM_DYN);

    conv_kernel<<<NN, 256>>>(A, t);
    gram_kernel<<<NTILES, 128, SMEM_DYN>>>();
    finalize_kernel<<<1, 1024>>>(out);
}